// round 2
// baseline (speedup 1.0000x reference)
#include <cuda_runtime.h>

#define QN 100
#define BB 8
#define CC 64
#define BCH 512          // B*C channels
#define HH 256
#define WW 256
#define TW 64
#define TH 32

// per-channel 18 filter coefficients (former[9], wk[9])
__device__ float g_coefs[BCH * 18];

// ---------------------------------------------------------------------------
// Kernel 1: conv1d = query^T @ Wl^T + bl  (per (b,c): 18 coefs),
//           q_out  = conv1d @ Wd^T + bd   (per (b,c): 100 outputs)
// ---------------------------------------------------------------------------
__global__ void __launch_bounds__(128) coef_q_kernel(
    const float* __restrict__ query,   // (100, 8, 64)
    const float* __restrict__ Wl,      // (18, 100)
    const float* __restrict__ bl,      // (18,)
    const float* __restrict__ Wd,      // (100, 18)
    const float* __restrict__ bd,      // (100,)
    float* __restrict__ q_out)         // (100, 8, 64)
{
    __shared__ float qs[QN];
    __shared__ float cv[18];
    int bc = blockIdx.x;
    int t  = threadIdx.x;

    if (t < QN) qs[t] = query[t * BCH + bc];
    __syncthreads();

    if (t < 18) {
        float s = bl[t];
        const float* wr = Wl + t * QN;
#pragma unroll 5
        for (int q = 0; q < QN; q++) s = fmaf(qs[q], wr[q], s);
        cv[t] = s;
        g_coefs[bc * 18 + t] = s;
    }
    __syncthreads();

    if (t < QN) {
        float s = bd[t];
        const float* wr = Wd + t * 18;
#pragma unroll
        for (int k = 0; k < 18; k++) s = fmaf(cv[k], wr[k], s);
        q_out[t * BCH + bc] = s;
    }
}

// ---------------------------------------------------------------------------
// Kernel 2: fused depthwise pipeline per channel tile.
//   y_temp = conv3x3(v, f)                       (SAME, zero pad)
//   d      = exp(-(v - y_temp)^2)   (0 outside image)
//   vd     = v * d
//   den    = conv3x3(d, |wk|) + 1e-10
//   num    = conv3x3(vd, w2), w2 = wk with middle row -> -(wk_top + wk_bot)
//            (this equals res - res_diff of the reference)
//   y      = y_temp - num / den
// ---------------------------------------------------------------------------
__global__ void __launch_bounds__(256) gc_main_kernel(
    const float* __restrict__ value,   // (512, 256, 256)
    float* __restrict__ y_out)         // (512, 256, 256)
{
    // width padded to 68 so every row base is 16B-aligned (68*4 = 272 = 17*16)
    __shared__ __align__(16) float Vs [36][68];  // v tile + halo 2
    __shared__ __align__(16) float Ds [34][68];  // d  on tile + halo 1 (cols 66,67 = pad)
    __shared__ __align__(16) float VDs[34][68];  // vd on tile + halo 1
    __shared__ __align__(16) float Ys [34][68];  // y_temp on tile + halo 1
    __shared__ float cf[18];

    const int t  = threadIdx.x;
    const int ch = blockIdx.z;
    const int x0 = blockIdx.x * TW;
    const int y0 = blockIdx.y * TH;
    const float* __restrict__ v = value + (size_t)ch * (HH * WW);

    if (t < 18) cf[t] = g_coefs[ch * 18 + t];

    // ---- load Vs: Vs[r][c] = v(y0 + r - 2, x0 + c - 2), zero outside image ----
    for (int idx = t; idx < 36 * 68; idx += 256) {
        int r = idx / 68, c = idx - r * 68;
        int gy = y0 + r - 2, gx = x0 + c - 2;
        float val = 0.f;
        if ((unsigned)gy < HH && (unsigned)gx < WW) val = v[gy * WW + gx];
        Vs[r][c] = val;
    }
    __syncthreads();

    float fk[9], wk[9];
#pragma unroll
    for (int i = 0; i < 9; i++) { fk[i] = cf[i]; wk[i] = cf[9 + i]; }

    // ---- pass 1: d, vd, y_temp over 34x66 region (tile + halo 1) ----
    // virtual 2x4 blocks: 17 row-blocks x 17 col-blocks = 289
#pragma unroll 1
    for (int blk = t; blk < 289; blk += 256) {
        int br = blk / 17, bcol = blk - br * 17;
        int r0 = br * 2, c0 = bcol * 4;

        float w[4][6];
#pragma unroll
        for (int i = 0; i < 4; i++) {
            float4 a = *(const float4*)&Vs[r0 + i][c0];
            w[i][0] = a.x; w[i][1] = a.y; w[i][2] = a.z; w[i][3] = a.w;
            if (c0 + 4 < 68) {
                float2 b2 = *(const float2*)&Vs[r0 + i][c0 + 4];
                w[i][4] = b2.x; w[i][5] = b2.y;
            } else {
                w[i][4] = 0.f; w[i][5] = 0.f;   // only last col-block (pad region)
            }
        }

#pragma unroll
        for (int pr = 0; pr < 2; pr++) {
            int rr = r0 + pr;                    // Ds row, <= 33
            int gy = y0 + rr - 1;
            float dv[4], vdv[4], ytv[4];
#pragma unroll
            for (int pc = 0; pc < 4; pc++) {
                float yt = 0.f;
#pragma unroll
                for (int i = 0; i < 3; i++)
#pragma unroll
                    for (int j = 0; j < 3; j++)
                        yt = fmaf(fk[i * 3 + j], w[pr + i][pc + j], yt);
                float vv = w[pr + 1][pc + 1];
                int gx = x0 + c0 + pc - 1;
                bool in = ((unsigned)gy < HH) && ((unsigned)gx < WW);
                float tt = vv - yt;
                float d  = in ? __expf(-tt * tt) : 0.f;  // zero pad for 2nd convs
                dv[pc] = d; vdv[pc] = vv * d; ytv[pc] = yt;
            }
            // cols 66,67 are padding, safe to store garbage there
            *(float4*)&Ds [rr][c0] = make_float4(dv[0],  dv[1],  dv[2],  dv[3]);
            *(float4*)&VDs[rr][c0] = make_float4(vdv[0], vdv[1], vdv[2], vdv[3]);
            *(float4*)&Ys [rr][c0] = make_float4(ytv[0], ytv[1], ytv[2], ytv[3]);
        }
    }
    __syncthreads();

    // ---- pass 2: den / num convs + final output, 4x2 px per thread ----
    float aa[9], w2[9];
#pragma unroll
    for (int i = 0; i < 9; i++) aa[i] = fabsf(wk[i]);
#pragma unroll
    for (int j = 0; j < 3; j++) {
        w2[j]     = wk[j];
        w2[3 + j] = -(wk[j] + wk[6 + j]);       // wk[1][j] - sum_i wk[i][j]
        w2[6 + j] = wk[6 + j];
    }

    const int c0 = (t & 15) * 4;   // 0..60
    const int r0 = (t >> 4) * 2;   // 0..30

    float den[2][4], num[2][4];
    {
        float w[4][6];
#pragma unroll
        for (int i = 0; i < 4; i++) {
            float4 a = *(const float4*)&Ds[r0 + i][c0];
            float2 b2 = *(const float2*)&Ds[r0 + i][c0 + 4];
            w[i][0]=a.x; w[i][1]=a.y; w[i][2]=a.z; w[i][3]=a.w; w[i][4]=b2.x; w[i][5]=b2.y;
        }
#pragma unroll
        for (int pr = 0; pr < 2; pr++)
#pragma unroll
            for (int pc = 0; pc < 4; pc++) {
                float s = 1e-10f;
#pragma unroll
                for (int i = 0; i < 3; i++)
#pragma unroll
                    for (int j = 0; j < 3; j++)
                        s = fmaf(aa[i * 3 + j], w[pr + i][pc + j], s);
                den[pr][pc] = s;
            }
    }
    {
        float w[4][6];
#pragma unroll
        for (int i = 0; i < 4; i++) {
            float4 a = *(const float4*)&VDs[r0 + i][c0];
            float2 b2 = *(const float2*)&VDs[r0 + i][c0 + 4];
            w[i][0]=a.x; w[i][1]=a.y; w[i][2]=a.z; w[i][3]=a.w; w[i][4]=b2.x; w[i][5]=b2.y;
        }
#pragma unroll
        for (int pr = 0; pr < 2; pr++)
#pragma unroll
            for (int pc = 0; pc < 4; pc++) {
                float s = 0.f;
#pragma unroll
                for (int i = 0; i < 3; i++)
#pragma unroll
                    for (int j = 0; j < 3; j++)
                        s = fmaf(w2[i * 3 + j], w[pr + i][pc + j], s);
                num[pr][pc] = s;
            }
    }

    float* __restrict__ yo = y_out + (size_t)ch * (HH * WW);
#pragma unroll
    for (int pr = 0; pr < 2; pr++) {
        int gy = y0 + r0 + pr;
        float o[4];
#pragma unroll
        for (int pc = 0; pc < 4; pc++) {
            float yt = Ys[r0 + pr + 1][c0 + pc + 1];
            o[pc] = yt - __fdividef(num[pr][pc], den[pr][pc]);
        }
        *(float4*)&yo[gy * WW + x0 + c0] = make_float4(o[0], o[1], o[2], o[3]);
    }
}

// ---------------------------------------------------------------------------
extern "C" void kernel_launch(void* const* d_in, const int* in_sizes, int n_in,
                              void* d_out, int out_size) {
    const float* query = (const float*)d_in[0];
    const float* value = (const float*)d_in[1];
    // d_in[2..4] = hard_sigmoid_masks, pos2, pos3 (unused by reference)
    const float* Wl = (const float*)d_in[5];
    const float* bl = (const float*)d_in[6];
    const float* Wd = (const float*)d_in[7];
    const float* bd = (const float*)d_in[8];

    float* out   = (float*)d_out;
    float* q_out = out;                       // (100, 8, 64) first
    float* y_out = out + QN * BB * CC;        // then (8, 64, 256, 256)

    coef_q_kernel<<<BCH, 128>>>(query, Wl, bl, Wd, bd, q_out);

    dim3 grid(WW / TW, HH / TH, BCH);         // (4, 8, 512)
    gc_main_kernel<<<grid, 256>>>(value, y_out);
}

// round 5
// speedup vs baseline: 1.1713x; 1.1713x over previous
#include <cuda_runtime.h>

#define QN 100
#define BB 8
#define CC 64
#define BCH 512          // B*C channels
#define HH 256
#define WW 256
#define TW 64
#define TH 32

// per-channel 18 filter coefficients (former[9], wk[9])
__device__ float g_coefs[BCH * 18];

// ---------------------------------------------------------------------------
// Kernel 1: conv1d = query^T @ Wl^T + bl  (per (b,c): 18 coefs),
//           q_out  = conv1d @ Wd^T + bd   (per (b,c): 100 outputs)
// ---------------------------------------------------------------------------
__global__ void __launch_bounds__(128) coef_q_kernel(
    const float* __restrict__ query,   // (100, 8, 64)
    const float* __restrict__ Wl,      // (18, 100)
    const float* __restrict__ bl,      // (18,)
    const float* __restrict__ Wd,      // (100, 18)
    const float* __restrict__ bd,      // (100,)
    float* __restrict__ q_out)         // (100, 8, 64)
{
    __shared__ float qs[QN];
    __shared__ float cv[18];
    int bc = blockIdx.x;
    int t  = threadIdx.x;

    if (t < QN) qs[t] = query[t * BCH + bc];
    __syncthreads();

    if (t < 18) {
        float s = bl[t];
        const float* wr = Wl + t * QN;
#pragma unroll 5
        for (int q = 0; q < QN; q++) s = fmaf(qs[q], wr[q], s);
        cv[t] = s;
        g_coefs[bc * 18 + t] = s;
    }
    __syncthreads();

    if (t < QN) {
        float s = bd[t];
        const float* wr = Wd + t * 18;
#pragma unroll
        for (int k = 0; k < 18; k++) s = fmaf(cv[k], wr[k], s);
        q_out[t * BCH + bc] = s;
    }
}

// ---------------------------------------------------------------------------
// Kernel 2: fused depthwise pipeline, one 64x32 tile of one channel per CTA.
//   y_temp = conv3x3(v, f)             (SAME, zero pad)
//   d      = exp(-(v - y_temp)^2)      (0 outside image -> border post-zero)
//   vd     = v * d
//   den    = conv3x3(d, |wk|) + 1e-10
//   num    = conv3x3(vd, w2), w2 = wk with middle row -> -(wk_top + wk_bot)
//   y      = y_temp - num / den
// ---------------------------------------------------------------------------
__global__ void __launch_bounds__(256, 5) gc_main_kernel(
    const float* __restrict__ value,   // (512, 256, 256)
    float* __restrict__ y_out)         // (512, 256, 256)
{
    // width padded to 68 so every row base is 16B-aligned
    __shared__ __align__(16) float Vs [36][68];  // v tile + halo 2
    __shared__ __align__(16) float Ds [34][68];  // d  on tile + halo 1
    __shared__ __align__(16) float VDs[34][68];  // vd on tile + halo 1
    __shared__ __align__(16) float Ys [34][68];  // y_temp on tile + halo 1
    __shared__ float cf[18];

    const int t  = threadIdx.x;
    const int ch = blockIdx.z;
    const int x0 = blockIdx.x * TW;
    const int y0 = blockIdx.y * TH;
    const float* __restrict__ v = value + (size_t)ch * (HH * WW);

    if (t < 18) cf[t] = g_coefs[ch * 18 + t];

    // ---- load Vs: Vs[r][c] = v(y0 + r - 2, x0 + c - 2), zero outside image ----
    for (int idx = t; idx < 36 * 68; idx += 256) {
        int r = idx / 68, c = idx - r * 68;
        int gy = y0 + r - 2, gx = x0 + c - 2;
        float val = 0.f;
        if ((unsigned)gy < HH && (unsigned)gx < WW) val = v[gy * WW + gx];
        Vs[r][c] = val;
    }
    __syncthreads();

    float fk[9];
#pragma unroll
    for (int i = 0; i < 9; i++) fk[i] = cf[i];

    // ---- pass 1: d, vd, y_temp over 34x66 region (tile + halo 1) ----
    // row-streamed: per 2x4 block, walk 4 input rows, keep only accumulators.
#pragma unroll 1
    for (int blk = t; blk < 289; blk += 256) {
        int br = blk / 17, bcol = blk - br * 17;
        int r0 = br * 2, c0 = bcol * 4;

        float yt0[4] = {0.f, 0.f, 0.f, 0.f};
        float yt1[4] = {0.f, 0.f, 0.f, 0.f};
        float vc0[4], vc1[4];

#pragma unroll
        for (int i = 0; i < 4; i++) {
            float w[6];
            float4 a = *(const float4*)&Vs[r0 + i][c0];
            w[0] = a.x; w[1] = a.y; w[2] = a.z; w[3] = a.w;
            if (c0 + 4 < 68) {
                float2 b2 = *(const float2*)&Vs[r0 + i][c0 + 4];
                w[4] = b2.x; w[5] = b2.y;
            } else { w[4] = 0.f; w[5] = 0.f; }

            if (i <= 2) {
#pragma unroll
                for (int pc = 0; pc < 4; pc++)
#pragma unroll
                    for (int j = 0; j < 3; j++)
                        yt0[pc] = fmaf(fk[i * 3 + j], w[pc + j], yt0[pc]);
            }
            if (i >= 1) {
#pragma unroll
                for (int pc = 0; pc < 4; pc++)
#pragma unroll
                    for (int j = 0; j < 3; j++)
                        yt1[pc] = fmaf(fk[(i - 1) * 3 + j], w[pc + j], yt1[pc]);
            }
            if (i == 1) {
#pragma unroll
                for (int pc = 0; pc < 4; pc++) vc0[pc] = w[pc + 1];
            }
            if (i == 2) {
#pragma unroll
                for (int pc = 0; pc < 4; pc++) vc1[pc] = w[pc + 1];
            }
        }

        float d0[4], d1[4], vd0[4], vd1[4];
#pragma unroll
        for (int pc = 0; pc < 4; pc++) {
            float tt = vc0[pc] - yt0[pc];
            d0[pc]  = __expf(-tt * tt);
            vd0[pc] = vc0[pc] * d0[pc];
            float uu = vc1[pc] - yt1[pc];
            d1[pc]  = __expf(-uu * uu);
            vd1[pc] = vc1[pc] * d1[pc];
        }
        // cols 66,67 are padding; safe to store garbage there
        *(float4*)&Ds [r0    ][c0] = make_float4(d0[0],  d0[1],  d0[2],  d0[3]);
        *(float4*)&Ds [r0 + 1][c0] = make_float4(d1[0],  d1[1],  d1[2],  d1[3]);
        *(float4*)&VDs[r0    ][c0] = make_float4(vd0[0], vd0[1], vd0[2], vd0[3]);
        *(float4*)&VDs[r0 + 1][c0] = make_float4(vd1[0], vd1[1], vd1[2], vd1[3]);
        *(float4*)&Ys [r0    ][c0] = make_float4(yt0[0], yt0[1], yt0[2], yt0[3]);
        *(float4*)&Ys [r0 + 1][c0] = make_float4(yt1[0], yt1[1], yt1[2], yt1[3]);
    }
    __syncthreads();

    // ---- zero d/vd on cells outside the image (CTA-uniform branch) ----
    const bool border = (y0 == 0) | (y0 + TH == HH) | (x0 == 0) | (x0 + TW == WW);
    if (border) {
        if (t < 68) {
            if (y0 == 0)       { Ds[0][t]  = 0.f; VDs[0][t]  = 0.f; }
            if (y0 + TH == HH) { Ds[33][t] = 0.f; VDs[33][t] = 0.f; }
        } else if (t >= 128 && t < 162) {
            int rr = t - 128;
            if (x0 == 0)       { Ds[rr][0]  = 0.f; VDs[rr][0]  = 0.f; }
            if (x0 + TW == WW) { Ds[rr][65] = 0.f; VDs[rr][65] = 0.f; }
        }
        __syncthreads();
    }

    // ---- pass 2: den / num convs + final output, 4x2 px per thread ----
    float aa[9], w2[9];
#pragma unroll
    for (int i = 0; i < 9; i++) aa[i] = fabsf(cf[9 + i]);
#pragma unroll
    for (int j = 0; j < 3; j++) {
        float wt = cf[9 + j], wb = cf[15 + j];
        w2[j]     = wt;
        w2[3 + j] = -(wt + wb);       // wk[1][j] - sum_i wk[i][j]
        w2[6 + j] = wb;
    }

    const int c0 = (t & 15) * 4;   // 0..60
    const int r0 = (t >> 4) * 2;   // 0..30

    float den[2][4] = {{1e-10f,1e-10f,1e-10f,1e-10f},{1e-10f,1e-10f,1e-10f,1e-10f}};
    float num[2][4] = {{0.f,0.f,0.f,0.f},{0.f,0.f,0.f,0.f}};

#pragma unroll
    for (int i = 0; i < 4; i++) {
        float w[6];
        {
            float4 a  = *(const float4*)&Ds[r0 + i][c0];
            float2 b2 = *(const float2*)&Ds[r0 + i][c0 + 4];
            w[0]=a.x; w[1]=a.y; w[2]=a.z; w[3]=a.w; w[4]=b2.x; w[5]=b2.y;
        }
        if (i <= 2) {
#pragma unroll
            for (int pc = 0; pc < 4; pc++)
#pragma unroll
                for (int j = 0; j < 3; j++)
                    den[0][pc] = fmaf(aa[i * 3 + j], w[pc + j], den[0][pc]);
        }
        if (i >= 1) {
#pragma unroll
            for (int pc = 0; pc < 4; pc++)
#pragma unroll
                for (int j = 0; j < 3; j++)
                    den[1][pc] = fmaf(aa[(i - 1) * 3 + j], w[pc + j], den[1][pc]);
        }
    }

#pragma unroll
    for (int i = 0; i < 4; i++) {
        float w[6];
        {
            float4 a  = *(const float4*)&VDs[r0 + i][c0];
            float2 b2 = *(const float2*)&VDs[r0 + i][c0 + 4];
            w[0]=a.x; w[1]=a.y; w[2]=a.z; w[3]=a.w; w[4]=b2.x; w[5]=b2.y;
        }
        if (i <= 2) {
#pragma unroll
            for (int pc = 0; pc < 4; pc++)
#pragma unroll
                for (int j = 0; j < 3; j++)
                    num[0][pc] = fmaf(w2[i * 3 + j], w[pc + j], num[0][pc]);
        }
        if (i >= 1) {
#pragma unroll
            for (int pc = 0; pc < 4; pc++)
#pragma unroll
                for (int j = 0; j < 3; j++)
                    num[1][pc] = fmaf(w2[(i - 1) * 3 + j], w[pc + j], num[1][pc]);
        }
    }

    float* __restrict__ yo = y_out + (size_t)ch * (HH * WW);
#pragma unroll
    for (int pr = 0; pr < 2; pr++) {
        float4 a  = *(const float4*)&Ys[r0 + pr + 1][c0];
        float2 b2 = *(const float2*)&Ys[r0 + pr + 1][c0 + 4];
        float yt[4] = {a.y, a.z, a.w, b2.x};
        float o[4];
#pragma unroll
        for (int pc = 0; pc < 4; pc++)
            o[pc] = yt[pc] - __fdividef(num[pr][pc], den[pr][pc]);
        int gy = y0 + r0 + pr;
        *(float4*)&yo[gy * WW + x0 + c0] = make_float4(o[0], o[1], o[2], o[3]);
    }
}

// ---------------------------------------------------------------------------
extern "C" void kernel_launch(void* const* d_in, const int* in_sizes, int n_in,
                              void* d_out, int out_size) {
    const float* query = (const float*)d_in[0];
    const float* value = (const float*)d_in[1];
    // d_in[2..4] = hard_sigmoid_masks, pos2, pos3 (unused by reference)
    const float* Wl = (const float*)d_in[5];
    const float* bl = (const float*)d_in[6];
    const float* Wd = (const float*)d_in[7];
    const float* bd = (const float*)d_in[8];

    float* out   = (float*)d_out;
    float* q_out = out;                       // (100, 8, 64) first
    float* y_out = out + QN * BB * CC;        // then (8, 64, 256, 256)

    coef_q_kernel<<<BCH, 128>>>(query, Wl, bl, Wd, bd, q_out);

    dim3 grid(WW / TW, HH / TH, BCH);         // (4, 8, 512)
    gc_main_kernel<<<grid, 256>>>(value, y_out);
}